// round 15
// baseline (speedup 1.0000x reference)
#include <cuda_runtime.h>
#include <cuda_fp16.h>
#include <cstdint>

#define CC 64
#define MAXB 16

// ---------------- device scratch (no allocations allowed) ----------------
__device__ float g_sums[MAXB * CC];                   // re-zeroed by prep phase (globals start zeroed)
__device__ __align__(16) float g_c[MAXB * CC];        // per-segment fused bias (BN folded)
__device__ __align__(16) uint32_t g_Wfrag[2048];      // B frags fp16: uint2 = {b0, b1} per (kt,n,lane)
__device__ unsigned int g_ctr;                        // last-block-done counter (self-resetting)

__device__ __forceinline__ uint32_t smem_u32(const void* p) {
    uint32_t a;
    asm("{ .reg .u64 t; cvta.to.shared.u64 t, %1; cvt.u32.u64 %0, t; }" : "=r"(a) : "l"(p));
    return a;
}

// ---------------- pass 1: segment sums + (last block) prep, fused ----------------
__global__ void k_segsum(const float4* __restrict__ x4, const int* __restrict__ o,
                         const float* __restrict__ W2, const float* __restrict__ b2,
                         const float* __restrict__ W1, const float* __restrict__ b1,
                         const float* __restrict__ gam, const float* __restrict__ bet,
                         const float* __restrict__ rmean, const float* __restrict__ rvar,
                         int N, int Bseg) {
    __shared__ int so[MAXB];
    __shared__ float4 red[256];
    __shared__ unsigned int isLast;
    // prep-phase storage (used only by the last block); 16B-aligned: accessed via float4 casts
    __shared__ __align__(16) float sW1[8192];      // 32 KB: full W1 [128][64]
    __shared__ __align__(16) float mh[1024];       // mean, then h
    __shared__ float ss[CC], st[CC];

    int t = threadIdx.x;
    if (t < Bseg) so[t] = o[t];
    __syncthreads();
    int c4 = t & 15, rg = t >> 4;
    int rpb = (N + gridDim.x - 1) / gridDim.x;
    int r0 = blockIdx.x * rpb;
    if (r0 < N) {
        int r1 = min(N, r0 + rpb);
        int s0 = 0; while (s0 < Bseg - 1 && r0 >= so[s0]) s0++;
        int s1 = s0; while (s1 < Bseg - 1 && (r1 - 1) >= so[s1]) s1++;
        if (s0 == s1) {
            float4 a0 = make_float4(0.f, 0.f, 0.f, 0.f);
            float4 a1 = make_float4(0.f, 0.f, 0.f, 0.f);
            float4 a2 = make_float4(0.f, 0.f, 0.f, 0.f);
            float4 a3 = make_float4(0.f, 0.f, 0.f, 0.f);
            int row = r0 + rg;
            for (; row + 48 < r1; row += 64) {
                float4 v0 = x4[(size_t)row * 16 + c4];
                float4 v1 = x4[(size_t)(row + 16) * 16 + c4];
                float4 v2 = x4[(size_t)(row + 32) * 16 + c4];
                float4 v3 = x4[(size_t)(row + 48) * 16 + c4];
                a0.x += v0.x; a0.y += v0.y; a0.z += v0.z; a0.w += v0.w;
                a1.x += v1.x; a1.y += v1.y; a1.z += v1.z; a1.w += v1.w;
                a2.x += v2.x; a2.y += v2.y; a2.z += v2.z; a2.w += v2.w;
                a3.x += v3.x; a3.y += v3.y; a3.z += v3.z; a3.w += v3.w;
            }
            for (; row < r1; row += 16) {
                float4 v = x4[(size_t)row * 16 + c4];
                a0.x += v.x; a0.y += v.y; a0.z += v.z; a0.w += v.w;
            }
            a0.x += a1.x + a2.x + a3.x; a0.y += a1.y + a2.y + a3.y;
            a0.z += a1.z + a2.z + a3.z; a0.w += a1.w + a2.w + a3.w;
            red[t] = a0;
            __syncthreads();
            #pragma unroll
            for (int s = 8; s >= 1; s >>= 1) {
                if (rg < s) {
                    float4 b = red[t + 16 * s];
                    float4 a = red[t];
                    a.x += b.x; a.y += b.y; a.z += b.z; a.w += b.w;
                    red[t] = a;
                }
                __syncthreads();
            }
            if (rg == 0) {
                float4 v = red[t];
                float* dst = &g_sums[s0 * CC + c4 * 4];
                atomicAdd(dst + 0, v.x); atomicAdd(dst + 1, v.y);
                atomicAdd(dst + 2, v.z); atomicAdd(dst + 3, v.w);
            }
        } else {
            int seg = s0;
            float4 a = make_float4(0.f, 0.f, 0.f, 0.f);
            for (int row = r0 + rg; row < r1; row += 16) {
                while (seg < Bseg - 1 && row >= so[seg]) {
                    float* dst = &g_sums[seg * CC + c4 * 4];
                    atomicAdd(dst + 0, a.x); atomicAdd(dst + 1, a.y);
                    atomicAdd(dst + 2, a.z); atomicAdd(dst + 3, a.w);
                    a = make_float4(0.f, 0.f, 0.f, 0.f);
                    seg++;
                }
                float4 v = x4[(size_t)row * 16 + c4];
                a.x += v.x; a.y += v.y; a.z += v.z; a.w += v.w;
            }
            float* dst = &g_sums[seg * CC + c4 * 4];
            atomicAdd(dst + 0, a.x); atomicAdd(dst + 1, a.y);
            atomicAdd(dst + 2, a.z); atomicAdd(dst + 3, a.w);
        }
    }

    // ---- last-block-done gate ----
    __threadfence();
    if (t == 0) {
        unsigned int c = atomicAdd(&g_ctr, 1u);
        isLast = (c == gridDim.x - 1) ? 1u : 0u;
    }
    __syncthreads();
    if (!isLast) return;

    // ======== PREP PHASE (last block only, 256 threads) ========
    // stage W1 (32 KB) coalesced: 8 float4 per thread
    {
        const float4* src = reinterpret_cast<const float4*>(W1);
        float4* dst = reinterpret_cast<float4*>(sW1);
        #pragma unroll
        for (int j = 0; j < 8; j++) dst[t + 256 * j] = src[t + 256 * j];
    }
    if (t < CC) {
        float sv = gam[t] * rsqrtf(rvar[t] + 1e-5f);
        ss[t] = sv;
        st[t] = bet[t] - rmean[t] * sv;
    }
    #pragma unroll
    for (int w = 0; w < 4; w++) {
        int i = t + 256 * w;
        if (i < Bseg * CC) {
            int b = i >> 6;
            int cnt = so[b] - (b ? so[b - 1] : 0);
            mh[i] = g_sums[i] / (float)cnt;
            g_sums[i] = 0.f;             // re-zero for next graph replay
        }
    }
    __syncthreads();

    // h = relu(mean @ W2 + b2) into registers
    float hv[4];
    #pragma unroll
    for (int w = 0; w < 4; w++) {
        int i = t + 256 * w;
        hv[w] = 0.f;
        if (i < Bseg * CC) {
            int b = i >> 6, j = i & 63;
            float acc = b2[j];
            #pragma unroll
            for (int k = 0; k < CC; k++) acc = fmaf(mh[b * CC + k], __ldg(&W2[k * CC + j]), acc);
            hv[w] = fmaxf(acc, 0.f);
        }
    }
    // B frag image (fp16): word i = ((kt*8 + n)*32 + lane)*2 + bslot
    //   frag col f = lane>>2, column PERMUTED for stmatrix-natural staging:
    //     n_col = n*8 + (f>>1) + (f&1)*4
    //   k2 = kt*16 + (lane&3)*2 + bslot*8;  W'[k][n] = W1[k*CC+n]*ss[n]
    #pragma unroll
    for (int w = 0; w < 8; w++) {
        int i = t + 256 * w;
        int bslot = i & 1;
        int lane = (i >> 1) & 31;
        int grp = i >> 6;
        int n = grp & 7;
        int kt = grp >> 3;
        int f = lane >> 2;
        int n_col = n * 8 + (f >> 1) + ((f & 1) << 2);
        int k2 = kt * 16 + (lane & 3) * 2 + bslot * 8;
        float sv = ss[n_col];
        float w0 = sW1[k2 * CC + n_col] * sv;
        float w1v = sW1[(k2 + 1) * CC + n_col] * sv;
        __half2 hp = __floats2half2_rn(w0, w1v);
        g_Wfrag[i] = *reinterpret_cast<uint32_t*>(&hp);
    }
    __syncthreads();
    #pragma unroll
    for (int w = 0; w < 4; w++) {
        int i = t + 256 * w;
        if (i < Bseg * CC) mh[i] = hv[w];
    }
    __syncthreads();
    // per-segment fused bias: c = (h @ W1_bot + b1) * ss + st
    #pragma unroll
    for (int w = 0; w < 4; w++) {
        int i = t + 256 * w;
        if (i < Bseg * CC) {
            int b = i >> 6, j = i & 63;
            float acc = b1[j];
            #pragma unroll
            for (int k = 0; k < CC; k++) acc = fmaf(mh[b * CC + k], sW1[(CC + k) * CC + j], acc);
            g_c[i] = acc * ss[j] + st[j];
        }
    }
    if (t == 0) g_ctr = 0;               // reset for next graph replay
}

// ---------------- MMA / ldmatrix / stmatrix helpers ----------------
__device__ __forceinline__ void mma16816h(float* c, const uint4& a, uint32_t b0, uint32_t b1) {
    asm volatile(
        "mma.sync.aligned.m16n8k16.row.col.f32.f16.f16.f32 "
        "{%0,%1,%2,%3}, {%4,%5,%6,%7}, {%8,%9}, {%0,%1,%2,%3};"
        : "+f"(c[0]), "+f"(c[1]), "+f"(c[2]), "+f"(c[3])
        : "r"(a.x), "r"(a.y), "r"(a.z), "r"(a.w), "r"(b0), "r"(b1));
}
__device__ __forceinline__ uint4 ldsm_x4(uint32_t addr) {
    uint4 r;
    asm volatile("ldmatrix.sync.aligned.m8n8.x4.shared.b16 {%0,%1,%2,%3}, [%4];"
        : "=r"(r.x), "=r"(r.y), "=r"(r.z), "=r"(r.w) : "r"(addr));
    return r;
}
__device__ __forceinline__ void stsm_x4(uint32_t addr, uint32_t r0, uint32_t r1,
                                        uint32_t r2, uint32_t r3) {
    asm volatile("stmatrix.sync.aligned.m8n8.x4.shared.b16 [%0], {%1,%2,%3,%4};"
        :: "r"(addr), "r"(r0), "r"(r1), "r"(r2), "r"(r3) : "memory");
}

// ---------------- pass 2: out = relu(x @ W' + c[seg]) via single-term fp16 HMMA ----------------
// A panel: fp16[128 rows][64 k], 128 B/row, SW128 swizzle, in buf[0..16384).
// After the MMA loop, buf is reused as fp32 output stage: 128 rows x 256 B,
// 16B chunk at (row, c16) at byte row*256 + ((c16*16) ^ ((row&7)<<4)).
struct __align__(1024) SmemM {
    unsigned char buf[32768];   // A panel (16 KB) -> fp32 stage (32 KB)
    uint2 Bimg[1024];           // 8 KB: {b0, b1} fp16 pairs per (kt,n,lane)
    float cbias[MAXB * CC];     // 4 KB: bias table
    unsigned char segb[128];
};

__global__ __launch_bounds__(256)
void k_main(const float4* __restrict__ x4, const int* __restrict__ o,
            float* __restrict__ out, int N, int Bseg) {
    __shared__ SmemM sm;
    int tid = threadIdx.x;
    int base = blockIdx.x * 128;

    // copy B frag image (8 KB) and bias table (4 KB), coalesced
    {
        const uint4* src = reinterpret_cast<const uint4*>(g_Wfrag);
        uint4* dst = reinterpret_cast<uint4*>(sm.Bimg);
        #pragma unroll
        for (int j = 0; j < 2; j++) dst[tid + 256 * j] = src[tid + 256 * j];
        reinterpret_cast<float4*>(sm.cbias)[tid] =
            reinterpret_cast<const float4*>(g_c)[tid];
    }
    // per-row segment ids
    if (tid < 128) {
        int row = min(base + tid, N - 1);
        int s = 0;
        while (s < Bseg - 1 && row >= __ldg(&o[s])) s++;
        sm.segb[tid] = (unsigned char)s;
    }

    // load x coalesced, round to fp16, STS.64 swizzled
    #pragma unroll
    for (int j = 0; j < 8; j++) {
        int idx = tid + 256 * j;
        int row = idx >> 4, c4 = idx & 15;
        int grow = base + row;
        float4 v = make_float4(0.f, 0.f, 0.f, 0.f);
        if (grow < N) v = x4[(size_t)grow * 16 + c4];

        __half2 h0 = __floats2half2_rn(v.x, v.y);
        __half2 h1 = __floats2half2_rn(v.z, v.w);
        uint32_t off = (uint32_t)(row * 128 + ((c4 * 8) ^ ((row & 7) << 4)));
        *reinterpret_cast<uint2*>(&sm.buf[off]) =
            make_uint2(*reinterpret_cast<uint32_t*>(&h0), *reinterpret_cast<uint32_t*>(&h1));
    }
    __syncthreads();

    int lane = tid & 31, wid = tid >> 5;
    int wm = wid & 3;      // row group: rows wm*32 .. +31
    int wn = wid >> 2;     // col group: cols wn*32 .. +31

    int lm = lane >> 3, lr = lane & 7;
    uint32_t a_base = smem_u32(sm.buf);
    uint32_t lane_row = (uint32_t)(wm * 32 + (lm & 1) * 8 + lr) * 128u;

    float acc[2][4][4];
    #pragma unroll
    for (int mb = 0; mb < 2; mb++)
        #pragma unroll
        for (int nt = 0; nt < 4; nt++)
            #pragma unroll
            for (int q = 0; q < 4; q++) acc[mb][nt][q] = 0.f;

    #pragma unroll
    for (int kt = 0; kt < 4; kt++) {
        uint32_t kcol = (uint32_t)((kt * 32 + (lm >> 1) * 16) ^ (lr << 4));
        uint4 ah[2];
        #pragma unroll
        for (int mb = 0; mb < 2; mb++)
            ah[mb] = ldsm_x4(a_base + lane_row + (uint32_t)(mb * 16 * 128) + kcol);
        #pragma unroll
        for (int nt = 0; nt < 4; nt++) {
            uint2 bv = sm.Bimg[(kt * 8 + wn * 4 + nt) * 32 + lane];
            #pragma unroll
            for (int mb = 0; mb < 2; mb++)
                mma16816h(acc[mb][nt], ah[mb], bv.x, bv.y);
        }
    }
    __syncthreads();   // all warps done reading A panel

    // stage accumulators via stmatrix.x4 (column-permuted B makes this row-natural)
    {
        int m = lane >> 3, rl8 = lane & 7;
        #pragma unroll
        for (int mb = 0; mb < 2; mb++) {
            int rrow = wm * 32 + mb * 16 + ((m & 1) << 3) + rl8;
            uint32_t rowb = a_base + (uint32_t)(rrow * 256);
            #pragma unroll
            for (int nt = 0; nt < 4; nt++) {
                int ci = wn * 8 + nt * 2 + (m >> 1);
                uint32_t addr = rowb + (uint32_t)((ci * 16) ^ (rl8 << 4));
                stsm_x4(addr,
                        __float_as_uint(acc[mb][nt][0]), __float_as_uint(acc[mb][nt][2]),
                        __float_as_uint(acc[mb][nt][1]), __float_as_uint(acc[mb][nt][3]));
            }
        }
    }
    __syncthreads();

    // read stage, add bias (SMEM), relu, coalesced STG.128
    float4* out4 = reinterpret_cast<float4*>(out);
    #pragma unroll
    for (int j = 0; j < 8; j++) {
        int idx = tid + 256 * j;
        int row = idx >> 4, c4 = idx & 15;
        int grow = base + row;
        if (grow < N) {
            const float4 v = *reinterpret_cast<const float4*>(
                &sm.buf[row * 256 + ((c4 * 16) ^ ((row & 7) << 4))]);
            int seg = sm.segb[row];
            const float4 b = *reinterpret_cast<const float4*>(&sm.cbias[seg * CC + c4 * 4]);
            float4 r;
            r.x = fmaxf(v.x + b.x, 0.f);
            r.y = fmaxf(v.y + b.y, 0.f);
            r.z = fmaxf(v.z + b.z, 0.f);
            r.w = fmaxf(v.w + b.w, 0.f);
            out4[(size_t)grow * 16 + c4] = r;
        }
    }
}

extern "C" void kernel_launch(void* const* d_in, const int* in_sizes, int n_in,
                              void* d_out, int out_size) {
    const float* x     = (const float*)d_in[0];
    const int*   o     = (const int*)  d_in[1];
    const float* W2    = (const float*)d_in[2];
    const float* b2    = (const float*)d_in[3];
    const float* W1    = (const float*)d_in[4];
    const float* b1    = (const float*)d_in[5];
    const float* gam   = (const float*)d_in[6];
    const float* bet   = (const float*)d_in[7];
    const float* rmean = (const float*)d_in[8];
    const float* rvar  = (const float*)d_in[9];
    float* out = (float*)d_out;

    int N = in_sizes[0] / CC;
    int B = in_sizes[1];

    k_segsum<<<1024, 256>>>((const float4*)x, o, W2, b2, W1, b1, gam, bet, rmean, rvar, N, B);
    k_main<<<(N + 127) / 128, 256>>>((const float4*)x, o, out, N, B);
}

// round 16
// speedup vs baseline: 1.0341x; 1.0341x over previous
#include <cuda_runtime.h>
#include <cuda_fp16.h>
#include <cstdint>

#define CC 64
#define MAXB 16

// ---------------- device scratch (no allocations allowed) ----------------
__device__ float g_sums[MAXB * CC];                   // re-zeroed by prep phase (globals start zeroed)
__device__ __align__(16) float g_c[MAXB * CC];        // per-segment fused bias (BN folded)
__device__ __align__(16) uint32_t g_Wfrag[2048];      // B frags fp16: uint2 = {b0, b1} per (kt,n,lane)
__device__ unsigned int g_ctr;                        // last-block-done counter (self-resetting)

__device__ __forceinline__ uint32_t smem_u32(const void* p) {
    uint32_t a;
    asm("{ .reg .u64 t; cvta.to.shared.u64 t, %1; cvt.u32.u64 %0, t; }" : "=r"(a) : "l"(p));
    return a;
}

// ---------------- pass 1: segment sums + (last block) prep, fused, minimal SMEM ----------------
__global__ void k_segsum(const float4* __restrict__ x4, const int* __restrict__ o,
                         const float* __restrict__ W2, const float* __restrict__ b2,
                         const float* __restrict__ W1, const float* __restrict__ b1,
                         const float* __restrict__ gam, const float* __restrict__ bet,
                         const float* __restrict__ rmean, const float* __restrict__ rvar,
                         int N, int Bseg) {
    __shared__ int so[MAXB];
    __shared__ __align__(16) float4 red[256];   // reduction; reused as mh[1024] in prep phase
    __shared__ unsigned int isLast;
    __shared__ float ss[CC], st[CC];            // prep only (512 B — occupancy-neutral)

    int t = threadIdx.x;
    if (t < Bseg) so[t] = o[t];
    __syncthreads();
    int c4 = t & 15, rg = t >> 4;
    int rpb = (N + gridDim.x - 1) / gridDim.x;
    int r0 = blockIdx.x * rpb;
    if (r0 < N) {
        int r1 = min(N, r0 + rpb);
        int s0 = 0; while (s0 < Bseg - 1 && r0 >= so[s0]) s0++;
        int s1 = s0; while (s1 < Bseg - 1 && (r1 - 1) >= so[s1]) s1++;
        if (s0 == s1) {
            float4 a0 = make_float4(0.f, 0.f, 0.f, 0.f);
            float4 a1 = make_float4(0.f, 0.f, 0.f, 0.f);
            float4 a2 = make_float4(0.f, 0.f, 0.f, 0.f);
            float4 a3 = make_float4(0.f, 0.f, 0.f, 0.f);
            int row = r0 + rg;
            for (; row + 48 < r1; row += 64) {
                float4 v0 = x4[(size_t)row * 16 + c4];
                float4 v1 = x4[(size_t)(row + 16) * 16 + c4];
                float4 v2 = x4[(size_t)(row + 32) * 16 + c4];
                float4 v3 = x4[(size_t)(row + 48) * 16 + c4];
                a0.x += v0.x; a0.y += v0.y; a0.z += v0.z; a0.w += v0.w;
                a1.x += v1.x; a1.y += v1.y; a1.z += v1.z; a1.w += v1.w;
                a2.x += v2.x; a2.y += v2.y; a2.z += v2.z; a2.w += v2.w;
                a3.x += v3.x; a3.y += v3.y; a3.z += v3.z; a3.w += v3.w;
            }
            for (; row < r1; row += 16) {
                float4 v = x4[(size_t)row * 16 + c4];
                a0.x += v.x; a0.y += v.y; a0.z += v.z; a0.w += v.w;
            }
            a0.x += a1.x + a2.x + a3.x; a0.y += a1.y + a2.y + a3.y;
            a0.z += a1.z + a2.z + a3.z; a0.w += a1.w + a2.w + a3.w;
            red[t] = a0;
            __syncthreads();
            #pragma unroll
            for (int s = 8; s >= 1; s >>= 1) {
                if (rg < s) {
                    float4 b = red[t + 16 * s];
                    float4 a = red[t];
                    a.x += b.x; a.y += b.y; a.z += b.z; a.w += b.w;
                    red[t] = a;
                }
                __syncthreads();
            }
            if (rg == 0) {
                float4 v = red[t];
                float* dst = &g_sums[s0 * CC + c4 * 4];
                atomicAdd(dst + 0, v.x); atomicAdd(dst + 1, v.y);
                atomicAdd(dst + 2, v.z); atomicAdd(dst + 3, v.w);
            }
        } else {
            int seg = s0;
            float4 a = make_float4(0.f, 0.f, 0.f, 0.f);
            for (int row = r0 + rg; row < r1; row += 16) {
                while (seg < Bseg - 1 && row >= so[seg]) {
                    float* dst = &g_sums[seg * CC + c4 * 4];
                    atomicAdd(dst + 0, a.x); atomicAdd(dst + 1, a.y);
                    atomicAdd(dst + 2, a.z); atomicAdd(dst + 3, a.w);
                    a = make_float4(0.f, 0.f, 0.f, 0.f);
                    seg++;
                }
                float4 v = x4[(size_t)row * 16 + c4];
                a.x += v.x; a.y += v.y; a.z += v.z; a.w += v.w;
            }
            float* dst = &g_sums[seg * CC + c4 * 4];
            atomicAdd(dst + 0, a.x); atomicAdd(dst + 1, a.y);
            atomicAdd(dst + 2, a.z); atomicAdd(dst + 3, a.w);
        }
    }

    // ---- last-block-done gate ----
    __threadfence();
    if (t == 0) {
        unsigned int c = atomicAdd(&g_ctr, 1u);
        isLast = (c == gridDim.x - 1) ? 1u : 0u;
    }
    __syncthreads();
    if (!isLast) return;

    // ======== PREP PHASE (last block only, 256 threads; latency-tolerant, __ldg weights) ========
    float* mh = reinterpret_cast<float*>(red);   // reuse reduction buffer as mh[1024]
    if (t < CC) {
        float sv = gam[t] * rsqrtf(rvar[t] + 1e-5f);
        ss[t] = sv;
        st[t] = bet[t] - rmean[t] * sv;
    }
    __syncthreads();   // all threads past reduction reads before mh overwrite
    #pragma unroll
    for (int w = 0; w < 4; w++) {
        int i = t + 256 * w;
        if (i < Bseg * CC) {
            int b = i >> 6;
            int cnt = so[b] - (b ? so[b - 1] : 0);
            mh[i] = g_sums[i] / (float)cnt;
            g_sums[i] = 0.f;             // re-zero for next graph replay
        }
    }
    __syncthreads();

    // h = relu(mean @ W2 + b2) into registers
    float hv[4];
    #pragma unroll
    for (int w = 0; w < 4; w++) {
        int i = t + 256 * w;
        hv[w] = 0.f;
        if (i < Bseg * CC) {
            int b = i >> 6, j = i & 63;
            float acc = b2[j];
            #pragma unroll
            for (int k = 0; k < CC; k++) acc = fmaf(mh[b * CC + k], __ldg(&W2[k * CC + j]), acc);
            hv[w] = fmaxf(acc, 0.f);
        }
    }
    // B frag image (fp16): word i = ((kt*8 + n)*32 + lane)*2 + bslot
    //   frag col f = lane>>2, column PERMUTED for stmatrix-natural staging:
    //     n_col = n*8 + (f>>1) + (f&1)*4
    //   k2 = kt*16 + (lane&3)*2 + bslot*8;  W'[k][n] = W1[k*CC+n]*ss[n]
    #pragma unroll
    for (int w = 0; w < 8; w++) {
        int i = t + 256 * w;
        int bslot = i & 1;
        int lane = (i >> 1) & 31;
        int grp = i >> 6;
        int n = grp & 7;
        int kt = grp >> 3;
        int f = lane >> 2;
        int n_col = n * 8 + (f >> 1) + ((f & 1) << 2);
        int k2 = kt * 16 + (lane & 3) * 2 + bslot * 8;
        float sv = ss[n_col];
        float w0 = __ldg(&W1[k2 * CC + n_col]) * sv;
        float w1v = __ldg(&W1[(k2 + 1) * CC + n_col]) * sv;
        __half2 hp = __floats2half2_rn(w0, w1v);
        g_Wfrag[i] = *reinterpret_cast<uint32_t*>(&hp);
    }
    __syncthreads();
    #pragma unroll
    for (int w = 0; w < 4; w++) {
        int i = t + 256 * w;
        if (i < Bseg * CC) mh[i] = hv[w];
    }
    __syncthreads();
    // per-segment fused bias: c = (h @ W1_bot + b1) * ss + st
    #pragma unroll
    for (int w = 0; w < 4; w++) {
        int i = t + 256 * w;
        if (i < Bseg * CC) {
            int b = i >> 6, j = i & 63;
            float acc = b1[j];
            #pragma unroll
            for (int k = 0; k < CC; k++) acc = fmaf(mh[b * CC + k], __ldg(&W1[(CC + k) * CC + j]), acc);
            g_c[i] = acc * ss[j] + st[j];
        }
    }
    if (t == 0) g_ctr = 0;               // reset for next graph replay
}

// ---------------- MMA / ldmatrix / stmatrix helpers ----------------
__device__ __forceinline__ void mma16816h(float* c, const uint4& a, uint32_t b0, uint32_t b1) {
    asm volatile(
        "mma.sync.aligned.m16n8k16.row.col.f32.f16.f16.f32 "
        "{%0,%1,%2,%3}, {%4,%5,%6,%7}, {%8,%9}, {%0,%1,%2,%3};"
        : "+f"(c[0]), "+f"(c[1]), "+f"(c[2]), "+f"(c[3])
        : "r"(a.x), "r"(a.y), "r"(a.z), "r"(a.w), "r"(b0), "r"(b1));
}
__device__ __forceinline__ uint4 ldsm_x4(uint32_t addr) {
    uint4 r;
    asm volatile("ldmatrix.sync.aligned.m8n8.x4.shared.b16 {%0,%1,%2,%3}, [%4];"
        : "=r"(r.x), "=r"(r.y), "=r"(r.z), "=r"(r.w) : "r"(addr));
    return r;
}
__device__ __forceinline__ void stsm_x4(uint32_t addr, uint32_t r0, uint32_t r1,
                                        uint32_t r2, uint32_t r3) {
    asm volatile("stmatrix.sync.aligned.m8n8.x4.shared.b16 [%0], {%1,%2,%3,%4};"
        :: "r"(addr), "r"(r0), "r"(r1), "r"(r2), "r"(r3) : "memory");
}

// ---------------- pass 2: out = relu(x @ W' + c[seg]) via single-term fp16 HMMA ----------------
// A panel: fp16[128 rows][64 k], 128 B/row, SW128 swizzle, in buf[0..16384).
// After the MMA loop, buf is reused as fp32 output stage: 128 rows x 256 B,
// 16B chunk at (row, c16) at byte row*256 + ((c16*16) ^ ((row&7)<<4)).
struct __align__(1024) SmemM {
    unsigned char buf[32768];   // A panel (16 KB) -> fp32 stage (32 KB)
    uint2 Bimg[1024];           // 8 KB: {b0, b1} fp16 pairs per (kt,n,lane)
    float cbias[MAXB * CC];     // 4 KB: bias table
    unsigned char segb[128];
};

__global__ __launch_bounds__(256)
void k_main(const float4* __restrict__ x4, const int* __restrict__ o,
            float* __restrict__ out, int N, int Bseg) {
    __shared__ SmemM sm;
    int tid = threadIdx.x;
    int base = blockIdx.x * 128;

    // copy B frag image (8 KB) and bias table (4 KB), coalesced
    {
        const uint4* src = reinterpret_cast<const uint4*>(g_Wfrag);
        uint4* dst = reinterpret_cast<uint4*>(sm.Bimg);
        #pragma unroll
        for (int j = 0; j < 2; j++) dst[tid + 256 * j] = src[tid + 256 * j];
        reinterpret_cast<float4*>(sm.cbias)[tid] =
            reinterpret_cast<const float4*>(g_c)[tid];
    }
    // per-row segment ids
    if (tid < 128) {
        int row = min(base + tid, N - 1);
        int s = 0;
        while (s < Bseg - 1 && row >= __ldg(&o[s])) s++;
        sm.segb[tid] = (unsigned char)s;
    }

    // load x coalesced, round to fp16, STS.64 swizzled
    #pragma unroll
    for (int j = 0; j < 8; j++) {
        int idx = tid + 256 * j;
        int row = idx >> 4, c4 = idx & 15;
        int grow = base + row;
        float4 v = make_float4(0.f, 0.f, 0.f, 0.f);
        if (grow < N) v = x4[(size_t)grow * 16 + c4];

        __half2 h0 = __floats2half2_rn(v.x, v.y);
        __half2 h1 = __floats2half2_rn(v.z, v.w);
        uint32_t off = (uint32_t)(row * 128 + ((c4 * 8) ^ ((row & 7) << 4)));
        *reinterpret_cast<uint2*>(&sm.buf[off]) =
            make_uint2(*reinterpret_cast<uint32_t*>(&h0), *reinterpret_cast<uint32_t*>(&h1));
    }
    __syncthreads();

    int lane = tid & 31, wid = tid >> 5;
    int wm = wid & 3;      // row group: rows wm*32 .. +31
    int wn = wid >> 2;     // col group: cols wn*32 .. +31

    int lm = lane >> 3, lr = lane & 7;
    uint32_t a_base = smem_u32(sm.buf);
    uint32_t lane_row = (uint32_t)(wm * 32 + (lm & 1) * 8 + lr) * 128u;

    float acc[2][4][4];
    #pragma unroll
    for (int mb = 0; mb < 2; mb++)
        #pragma unroll
        for (int nt = 0; nt < 4; nt++)
            #pragma unroll
            for (int q = 0; q < 4; q++) acc[mb][nt][q] = 0.f;

    #pragma unroll
    for (int kt = 0; kt < 4; kt++) {
        uint32_t kcol = (uint32_t)((kt * 32 + (lm >> 1) * 16) ^ (lr << 4));
        uint4 ah[2];
        #pragma unroll
        for (int mb = 0; mb < 2; mb++)
            ah[mb] = ldsm_x4(a_base + lane_row + (uint32_t)(mb * 16 * 128) + kcol);
        #pragma unroll
        for (int nt = 0; nt < 4; nt++) {
            uint2 bv = sm.Bimg[(kt * 8 + wn * 4 + nt) * 32 + lane];
            #pragma unroll
            for (int mb = 0; mb < 2; mb++)
                mma16816h(acc[mb][nt], ah[mb], bv.x, bv.y);
        }
    }
    __syncthreads();   // all warps done reading A panel

    // stage accumulators via stmatrix.x4 (column-permuted B makes this row-natural)
    {
        int m = lane >> 3, rl8 = lane & 7;
        #pragma unroll
        for (int mb = 0; mb < 2; mb++) {
            int rrow = wm * 32 + mb * 16 + ((m & 1) << 3) + rl8;
            uint32_t rowb = a_base + (uint32_t)(rrow * 256);
            #pragma unroll
            for (int nt = 0; nt < 4; nt++) {
                int ci = wn * 8 + nt * 2 + (m >> 1);
                uint32_t addr = rowb + (uint32_t)((ci * 16) ^ (rl8 << 4));
                stsm_x4(addr,
                        __float_as_uint(acc[mb][nt][0]), __float_as_uint(acc[mb][nt][2]),
                        __float_as_uint(acc[mb][nt][1]), __float_as_uint(acc[mb][nt][3]));
            }
        }
    }
    __syncthreads();

    // read stage, add bias (SMEM), relu, coalesced STG.128
    float4* out4 = reinterpret_cast<float4*>(out);
    #pragma unroll
    for (int j = 0; j < 8; j++) {
        int idx = tid + 256 * j;
        int row = idx >> 4, c4 = idx & 15;
        int grow = base + row;
        if (grow < N) {
            const float4 v = *reinterpret_cast<const float4*>(
                &sm.buf[row * 256 + ((c4 * 16) ^ ((row & 7) << 4))]);
            int seg = sm.segb[row];
            const float4 b = *reinterpret_cast<const float4*>(&sm.cbias[seg * CC + c4 * 4]);
            float4 r;
            r.x = fmaxf(v.x + b.x, 0.f);
            r.y = fmaxf(v.y + b.y, 0.f);
            r.z = fmaxf(v.z + b.z, 0.f);
            r.w = fmaxf(v.w + b.w, 0.f);
            out4[(size_t)grow * 16 + c4] = r;
        }
    }
}

extern "C" void kernel_launch(void* const* d_in, const int* in_sizes, int n_in,
                              void* d_out, int out_size) {
    const float* x     = (const float*)d_in[0];
    const int*   o     = (const int*)  d_in[1];
    const float* W2    = (const float*)d_in[2];
    const float* b2    = (const float*)d_in[3];
    const float* W1    = (const float*)d_in[4];
    const float* b1    = (const float*)d_in[5];
    const float* gam   = (const float*)d_in[6];
    const float* bet   = (const float*)d_in[7];
    const float* rmean = (const float*)d_in[8];
    const float* rvar  = (const float*)d_in[9];
    float* out = (float*)d_out;

    int N = in_sizes[0] / CC;
    int B = in_sizes[1];

    k_segsum<<<1024, 256>>>((const float4*)x, o, W2, b2, W1, b1, gam, bet, rmean, rvar, N, B);
    k_main<<<(N + 127) / 128, 256>>>((const float4*)x, o, out, N, B);
}

// round 17
// speedup vs baseline: 1.0561x; 1.0213x over previous
#include <cuda_runtime.h>
#include <cuda_fp16.h>
#include <cstdint>

#define CC 64
#define MAXB 16

// ---------------- device scratch (no allocations allowed) ----------------
__device__ float g_sums[MAXB * CC];                   // re-zeroed by k_prep after use (globals start zeroed)
__device__ __align__(16) float g_c[MAXB * CC];        // per-segment fused bias (BN folded)
__device__ __align__(16) uint32_t g_Wfrag[2048];      // B frags fp16: uint2 = {b0, b1} per (kt,n,lane)

__device__ __forceinline__ uint32_t smem_u32(const void* p) {
    uint32_t a;
    asm("{ .reg .u64 t; cvta.to.shared.u64 t, %1; cvt.u32.u64 %0, t; }" : "=r"(a) : "l"(p));
    return a;
}
// PDL primitives (sm_90+)
__device__ __forceinline__ void gdc_launch_dependents() {
    asm volatile("griddepcontrol.launch_dependents;");
}
__device__ __forceinline__ void gdc_wait() {
    asm volatile("griddepcontrol.wait;" ::: "memory");
}

// ---------------- pass 1: segment sums (float4, MLP=4, smem tree, few atomics) ----------------
__global__ void k_segsum(const float4* __restrict__ x4, const int* __restrict__ o,
                         int N, int Bseg) {
    __shared__ int so[MAXB];
    __shared__ float4 red[256];
    int t = threadIdx.x;
    if (t < Bseg) so[t] = o[t];
    __syncthreads();
    int c4 = t & 15, rg = t >> 4;
    int rpb = (N + gridDim.x - 1) / gridDim.x;
    int r0 = blockIdx.x * rpb;
    if (r0 < N) {
        int r1 = min(N, r0 + rpb);
        int s0 = 0; while (s0 < Bseg - 1 && r0 >= so[s0]) s0++;
        int s1 = s0; while (s1 < Bseg - 1 && (r1 - 1) >= so[s1]) s1++;
        if (s0 == s1) {
            float4 a0 = make_float4(0.f, 0.f, 0.f, 0.f);
            float4 a1 = make_float4(0.f, 0.f, 0.f, 0.f);
            float4 a2 = make_float4(0.f, 0.f, 0.f, 0.f);
            float4 a3 = make_float4(0.f, 0.f, 0.f, 0.f);
            int row = r0 + rg;
            for (; row + 48 < r1; row += 64) {
                float4 v0 = x4[(size_t)row * 16 + c4];
                float4 v1 = x4[(size_t)(row + 16) * 16 + c4];
                float4 v2 = x4[(size_t)(row + 32) * 16 + c4];
                float4 v3 = x4[(size_t)(row + 48) * 16 + c4];
                a0.x += v0.x; a0.y += v0.y; a0.z += v0.z; a0.w += v0.w;
                a1.x += v1.x; a1.y += v1.y; a1.z += v1.z; a1.w += v1.w;
                a2.x += v2.x; a2.y += v2.y; a2.z += v2.z; a2.w += v2.w;
                a3.x += v3.x; a3.y += v3.y; a3.z += v3.z; a3.w += v3.w;
            }
            for (; row < r1; row += 16) {
                float4 v = x4[(size_t)row * 16 + c4];
                a0.x += v.x; a0.y += v.y; a0.z += v.z; a0.w += v.w;
            }
            a0.x += a1.x + a2.x + a3.x; a0.y += a1.y + a2.y + a3.y;
            a0.z += a1.z + a2.z + a3.z; a0.w += a1.w + a2.w + a3.w;
            red[t] = a0;
            __syncthreads();
            #pragma unroll
            for (int s = 8; s >= 1; s >>= 1) {
                if (rg < s) {
                    float4 b = red[t + 16 * s];
                    float4 a = red[t];
                    a.x += b.x; a.y += b.y; a.z += b.z; a.w += b.w;
                    red[t] = a;
                }
                __syncthreads();
            }
            if (rg == 0) {
                float4 v = red[t];
                float* dst = &g_sums[s0 * CC + c4 * 4];
                atomicAdd(dst + 0, v.x); atomicAdd(dst + 1, v.y);
                atomicAdd(dst + 2, v.z); atomicAdd(dst + 3, v.w);
            }
        } else {
            int seg = s0;
            float4 a = make_float4(0.f, 0.f, 0.f, 0.f);
            for (int row = r0 + rg; row < r1; row += 16) {
                while (seg < Bseg - 1 && row >= so[seg]) {
                    float* dst = &g_sums[seg * CC + c4 * 4];
                    atomicAdd(dst + 0, a.x); atomicAdd(dst + 1, a.y);
                    atomicAdd(dst + 2, a.z); atomicAdd(dst + 3, a.w);
                    a = make_float4(0.f, 0.f, 0.f, 0.f);
                    seg++;
                }
                float4 v = x4[(size_t)row * 16 + c4];
                a.x += v.x; a.y += v.y; a.z += v.z; a.w += v.w;
            }
            float* dst = &g_sums[seg * CC + c4 * 4];
            atomicAdd(dst + 0, a.x); atomicAdd(dst + 1, a.y);
            atomicAdd(dst + 2, a.z); atomicAdd(dst + 3, a.w);
        }
    }
    gdc_launch_dependents();   // all work + atomics issued: let k_prep schedule
}

// ---------------- pass 2 (tiny, PDL): overlap weight staging with segsum ----------------
__global__ void k_prep(const int* __restrict__ o, const float* __restrict__ W2,
                       const float* __restrict__ b2, const float* __restrict__ W1,
                       const float* __restrict__ b1, const float* __restrict__ gam,
                       const float* __restrict__ bet, const float* __restrict__ rmean,
                       const float* __restrict__ rvar, int Bseg) {
    __shared__ __align__(16) float sW2[4096];    // 16 KB
    __shared__ __align__(16) float sW1b[4096];   // 16 KB (W1 bottom half)
    __shared__ __align__(16) float mh[1024];
    __shared__ float ss[CC], st[CC];
    int t = threadIdx.x;                          // 0..1023
    gdc_launch_dependents();                      // let k_main schedule immediately

    // ---- segsum-independent work (overlap window) ----
    reinterpret_cast<float4*>(sW2)[t]  = __ldg(&reinterpret_cast<const float4*>(W2)[t]);
    reinterpret_cast<float4*>(sW1b)[t] = __ldg(&reinterpret_cast<const float4*>(W1)[1024 + t]);
    if (t < CC) {
        float sv = gam[t] * rsqrtf(rvar[t] + 1e-5f);
        ss[t] = sv;
        st[t] = bet[t] - rmean[t] * sv;
    }
    __syncthreads();
    // B frag image (fp16): word i = ((kt*8 + n)*32 + lane)*2 + bslot
    //   frag col f = lane>>2, column PERMUTED for stmatrix-natural staging:
    //     n_col = n*8 + (f>>1) + (f&1)*4
    //   k2 = kt*16 + (lane&3)*2 + bslot*8  (top half of W1 only)
    #pragma unroll
    for (int w = 0; w < 2; w++) {
        int i = t + 1024 * w;
        int bslot = i & 1;
        int lane = (i >> 1) & 31;
        int grp = i >> 6;
        int n = grp & 7;
        int kt = grp >> 3;
        int f = lane >> 2;
        int n_col = n * 8 + (f >> 1) + ((f & 1) << 2);
        int k2 = kt * 16 + (lane & 3) * 2 + bslot * 8;
        float sv = ss[n_col];
        float w0 = __ldg(&W1[k2 * CC + n_col]) * sv;
        float w1v = __ldg(&W1[(k2 + 1) * CC + n_col]) * sv;
        __half2 hp = __floats2half2_rn(w0, w1v);
        g_Wfrag[i] = *reinterpret_cast<uint32_t*>(&hp);
    }

    // ---- wait for segsum's sums, then the short MLP chain at LDS speed ----
    gdc_wait();
    if (t < Bseg * CC) {
        int b = t >> 6;
        int cnt = __ldg(&o[b]) - (b ? __ldg(&o[b - 1]) : 0);
        mh[t] = g_sums[t] / (float)cnt;
        g_sums[t] = 0.f;                 // re-zero for next graph replay
    }
    __syncthreads();
    float hval = 0.f;
    if (t < Bseg * CC) {
        int b = t >> 6, j = t & 63;
        float acc = b2[j];
        #pragma unroll
        for (int k = 0; k < CC; k++) acc = fmaf(mh[b * CC + k], sW2[k * CC + j], acc);
        hval = fmaxf(acc, 0.f);
    }
    __syncthreads();
    if (t < Bseg * CC) mh[t] = hval;
    __syncthreads();
    if (t < Bseg * CC) {
        int b = t >> 6, j = t & 63;
        float acc = b1[j];
        #pragma unroll
        for (int k = 0; k < CC; k++) acc = fmaf(mh[b * CC + k], sW1b[k * CC + j], acc);
        g_c[t] = acc * ss[j] + st[j];
    }
}

// ---------------- MMA / ldmatrix / stmatrix helpers ----------------
__device__ __forceinline__ void mma16816h(float* c, const uint4& a, uint32_t b0, uint32_t b1) {
    asm volatile(
        "mma.sync.aligned.m16n8k16.row.col.f32.f16.f16.f32 "
        "{%0,%1,%2,%3}, {%4,%5,%6,%7}, {%8,%9}, {%0,%1,%2,%3};"
        : "+f"(c[0]), "+f"(c[1]), "+f"(c[2]), "+f"(c[3])
        : "r"(a.x), "r"(a.y), "r"(a.z), "r"(a.w), "r"(b0), "r"(b1));
}
__device__ __forceinline__ uint4 ldsm_x4(uint32_t addr) {
    uint4 r;
    asm volatile("ldmatrix.sync.aligned.m8n8.x4.shared.b16 {%0,%1,%2,%3}, [%4];"
        : "=r"(r.x), "=r"(r.y), "=r"(r.z), "=r"(r.w) : "r"(addr));
    return r;
}
__device__ __forceinline__ void stsm_x4(uint32_t addr, uint32_t r0, uint32_t r1,
                                        uint32_t r2, uint32_t r3) {
    asm volatile("stmatrix.sync.aligned.m8n8.x4.shared.b16 [%0], {%1,%2,%3,%4};"
        :: "r"(addr), "r"(r0), "r"(r1), "r"(r2), "r"(r3) : "memory");
}

// ---------------- pass 3 (PDL): out = relu(x @ W' + c[seg]) via single-term fp16 HMMA ----------------
// A panel: fp16[128 rows][64 k], 128 B/row, SW128 swizzle, in buf[0..16384).
// After the MMA loop, buf is reused as fp32 output stage: 128 rows x 256 B,
// 16B chunk at (row, c16) at byte row*256 + ((c16*16) ^ ((row&7)<<4)).
struct __align__(1024) SmemM {
    unsigned char buf[32768];   // A panel (16 KB) -> fp32 stage (32 KB)
    uint2 Bimg[1024];           // 8 KB: {b0, b1} fp16 pairs per (kt,n,lane)
    float cbias[MAXB * CC];     // 4 KB: bias table
    unsigned char segb[128];
};

__global__ __launch_bounds__(256)
void k_main(const float4* __restrict__ x4, const int* __restrict__ o,
            float* __restrict__ out, int N, int Bseg) {
    __shared__ SmemM sm;
    int tid = threadIdx.x;
    int base = blockIdx.x * 128;

    // ---- prep-independent: per-row segment ids + x load/convert (overlap window) ----
    if (tid < 128) {
        int row = min(base + tid, N - 1);
        int s = 0;
        while (s < Bseg - 1 && row >= __ldg(&o[s])) s++;
        sm.segb[tid] = (unsigned char)s;
    }
    #pragma unroll
    for (int j = 0; j < 8; j++) {
        int idx = tid + 256 * j;
        int row = idx >> 4, c4 = idx & 15;
        int grow = base + row;
        float4 v = make_float4(0.f, 0.f, 0.f, 0.f);
        if (grow < N) v = x4[(size_t)grow * 16 + c4];

        __half2 h0 = __floats2half2_rn(v.x, v.y);
        __half2 h1 = __floats2half2_rn(v.z, v.w);
        uint32_t off = (uint32_t)(row * 128 + ((c4 * 8) ^ ((row & 7) << 4)));
        *reinterpret_cast<uint2*>(&sm.buf[off]) =
            make_uint2(*reinterpret_cast<uint32_t*>(&h0), *reinterpret_cast<uint32_t*>(&h1));
    }

    // ---- wait for k_prep's Wfrag/g_c, then copy them to SMEM ----
    gdc_wait();
    {
        const uint4* src = reinterpret_cast<const uint4*>(g_Wfrag);
        uint4* dst = reinterpret_cast<uint4*>(sm.Bimg);
        #pragma unroll
        for (int j = 0; j < 2; j++) dst[tid + 256 * j] = src[tid + 256 * j];
        reinterpret_cast<float4*>(sm.cbias)[tid] =
            reinterpret_cast<const float4*>(g_c)[tid];
    }
    __syncthreads();

    int lane = tid & 31, wid = tid >> 5;
    int wm = wid & 3;      // row group: rows wm*32 .. +31
    int wn = wid >> 2;     // col group: cols wn*32 .. +31

    int lm = lane >> 3, lr = lane & 7;
    uint32_t a_base = smem_u32(sm.buf);
    uint32_t lane_row = (uint32_t)(wm * 32 + (lm & 1) * 8 + lr) * 128u;

    float acc[2][4][4];
    #pragma unroll
    for (int mb = 0; mb < 2; mb++)
        #pragma unroll
        for (int nt = 0; nt < 4; nt++)
            #pragma unroll
            for (int q = 0; q < 4; q++) acc[mb][nt][q] = 0.f;

    #pragma unroll
    for (int kt = 0; kt < 4; kt++) {
        uint32_t kcol = (uint32_t)((kt * 32 + (lm >> 1) * 16) ^ (lr << 4));
        uint4 ah[2];
        #pragma unroll
        for (int mb = 0; mb < 2; mb++)
            ah[mb] = ldsm_x4(a_base + lane_row + (uint32_t)(mb * 16 * 128) + kcol);
        #pragma unroll
        for (int nt = 0; nt < 4; nt++) {
            uint2 bv = sm.Bimg[(kt * 8 + wn * 4 + nt) * 32 + lane];
            #pragma unroll
            for (int mb = 0; mb < 2; mb++)
                mma16816h(acc[mb][nt], ah[mb], bv.x, bv.y);
        }
    }
    __syncthreads();   // all warps done reading A panel

    // stage accumulators via stmatrix.x4 (column-permuted B makes this row-natural)
    {
        int m = lane >> 3, rl8 = lane & 7;
        #pragma unroll
        for (int mb = 0; mb < 2; mb++) {
            int rrow = wm * 32 + mb * 16 + ((m & 1) << 3) + rl8;
            uint32_t rowb = a_base + (uint32_t)(rrow * 256);
            #pragma unroll
            for (int nt = 0; nt < 4; nt++) {
                int ci = wn * 8 + nt * 2 + (m >> 1);
                uint32_t addr = rowb + (uint32_t)((ci * 16) ^ (rl8 << 4));
                stsm_x4(addr,
                        __float_as_uint(acc[mb][nt][0]), __float_as_uint(acc[mb][nt][2]),
                        __float_as_uint(acc[mb][nt][1]), __float_as_uint(acc[mb][nt][3]));
            }
        }
    }
    __syncthreads();

    // read stage, add bias (SMEM), relu, coalesced STG.128
    float4* out4 = reinterpret_cast<float4*>(out);
    #pragma unroll
    for (int j = 0; j < 8; j++) {
        int idx = tid + 256 * j;
        int row = idx >> 4, c4 = idx & 15;
        int grow = base + row;
        if (grow < N) {
            const float4 v = *reinterpret_cast<const float4*>(
                &sm.buf[row * 256 + ((c4 * 16) ^ ((row & 7) << 4))]);
            int seg = sm.segb[row];
            const float4 b = *reinterpret_cast<const float4*>(&sm.cbias[seg * CC + c4 * 4]);
            float4 r;
            r.x = fmaxf(v.x + b.x, 0.f);
            r.y = fmaxf(v.y + b.y, 0.f);
            r.z = fmaxf(v.z + b.z, 0.f);
            r.w = fmaxf(v.w + b.w, 0.f);
            out4[(size_t)grow * 16 + c4] = r;
        }
    }
}

extern "C" void kernel_launch(void* const* d_in, const int* in_sizes, int n_in,
                              void* d_out, int out_size) {
    const float* x     = (const float*)d_in[0];
    const int*   o     = (const int*)  d_in[1];
    const float* W2    = (const float*)d_in[2];
    const float* b2    = (const float*)d_in[3];
    const float* W1    = (const float*)d_in[4];
    const float* b1    = (const float*)d_in[5];
    const float* gam   = (const float*)d_in[6];
    const float* bet   = (const float*)d_in[7];
    const float* rmean = (const float*)d_in[8];
    const float* rvar  = (const float*)d_in[9];
    float* out = (float*)d_out;

    int N = in_sizes[0] / CC;
    int B = in_sizes[1];

    k_segsum<<<1024, 256>>>((const float4*)x, o, N, B);

    cudaLaunchAttribute pdl[1];
    pdl[0].id = cudaLaunchAttributeProgrammaticStreamSerialization;
    pdl[0].val.programmaticStreamSerializationAllowed = 1;

    cudaLaunchConfig_t c2 = {};
    c2.gridDim = dim3(1);
    c2.blockDim = dim3(1024);
    c2.attrs = pdl;
    c2.numAttrs = 1;
    cudaLaunchKernelEx(&c2, k_prep, o, W2, b2, W1, b1, gam, bet, rmean, rvar, B);

    cudaLaunchConfig_t c3 = {};
    c3.gridDim = dim3((unsigned)((N + 127) / 128));
    c3.blockDim = dim3(256);
    c3.attrs = pdl;
    c3.numAttrs = 1;
    cudaLaunchKernelEx(&c3, k_main, (const float4*)x, o, out, N, B);
}